// round 4
// baseline (speedup 1.0000x reference)
#include <cuda_runtime.h>
#include <cuda_bf16.h>
#include <math.h>

// ---------------------------------------------------------------------------
// ViT-Base forward: B=32, S=197, E=768, H=12, D=64, FC=3072, L=12
// Round 3: tensor-core GEMM via mma.sync bf16 with 2-term (hi/lo) split
//          => fp32-grade accuracy at tensor-core speed.
// ---------------------------------------------------------------------------

#define BATCH 32
#define SEQ   197
#define EMB   768
#define HEADS 12
#define HDIM  64
#define FFN   3072
#define LAYERS 12
#define NPATCH 196
#define ROWS  (BATCH * SEQ)      // 6304
#define PROWS (BATCH * NPATCH)   // 6272

__device__ float g_x  [ROWS * EMB];
__device__ float g_q  [ROWS * EMB];
__device__ float g_k  [ROWS * EMB];
__device__ float g_v  [ROWS * EMB];
__device__ float g_o  [ROWS * EMB];
__device__ float g_t2 [ROWS * EMB];
__device__ float g_t1 [ROWS * FFN];
__device__ float g_pos[SEQ * EMB];

// ---------------------------------------------------------------------------
// Patchify
// ---------------------------------------------------------------------------
__global__ void patchify_kernel(const float* __restrict__ img, float* __restrict__ out) {
    int idx = blockIdx.x * 256 + threadIdx.x;
    if (idx >= PROWS * EMB) return;
    int col = idx % EMB;
    int row = idx / EMB;
    int b = row / NPATCH, p = row % NPATCH;
    int hh = p / 14, ww = p % 14;
    int c = col % 3;
    int pp = col / 3;
    int p1 = pp / 16, p2 = pp % 16;
    out[idx] = img[((b * 3 + c) * 224 + hh * 16 + p1) * 224 + ww * 16 + p2];
}

// ---------------------------------------------------------------------------
// 2D sincos positional encoding
// ---------------------------------------------------------------------------
__global__ void pos_kernel(float* __restrict__ pos) {
    int idx = blockIdx.x * 256 + threadIdx.x;
    if (idx >= SEQ * EMB) return;
    int t = idx / EMB, j = idx % EMB;
    float val = 0.f;
    if (t > 0) {
        int tok = t - 1;
        int quad = j / 192;
        int i = j % 192;
        float omega = expf(-((float)i / 191.f) * logf(10000.f));
        float coord = (quad < 2) ? (float)(tok % 14) : (float)(tok / 14);
        float arg = coord * omega;
        val = (quad & 1) ? cosf(arg) : sinf(arg);
    }
    pos[idx] = val;
}

// ---------------------------------------------------------------------------
// Assemble tokens
// ---------------------------------------------------------------------------
__global__ void assemble_kernel(const float* __restrict__ emb, const float* __restrict__ cls,
                                const float* __restrict__ pos, float* __restrict__ x) {
    int idx = blockIdx.x * 256 + threadIdx.x;
    if (idx >= ROWS * EMB) return;
    int e = idx % EMB;
    int bs = idx / EMB;
    int s = bs % SEQ, b = bs / SEQ;
    float val;
    if (s == 0) val = cls[e];
    else        val = emb[(b * NPATCH + s - 1) * EMB + e] + pos[s * EMB + e];
    x[idx] = val;
}

// ---------------------------------------------------------------------------
// Tensor-core GEMM: C[M,N] = A[M,K] @ B[K,N] (+bias)(+exact GELU)
// bf16 2-term split; 128x128x32 block tile; 8 warps (2m x 4n), 64x32 warp tile.
// Requires K%32==0, N%128==0. M arbitrary.
// ---------------------------------------------------------------------------
#define BM 128
#define BN 128
#define BK 32
#define SAS 40    // As row stride in bf16 (32 + 8 pad) -> conflict-free LDSM
#define SBS 136   // Bs row stride in bf16 (128 + 8 pad)

__device__ __forceinline__ unsigned su32(const void* p) {
    return (unsigned)__cvta_generic_to_shared(p);
}

__device__ __forceinline__ void split2(float x, float y, unsigned& hi, unsigned& lo_) {
    // pack bf16(x),bf16(y) into hi (x in low half); residuals into lo_
    __nv_bfloat162 h = __floats2bfloat162_rn(x, y);
    float rx = x - __bfloat162float(h.x);
    float ry = y - __bfloat162float(h.y);
    __nv_bfloat162 l = __floats2bfloat162_rn(rx, ry);
    hi  = *(unsigned*)&h;
    lo_ = *(unsigned*)&l;
}

__device__ __forceinline__ void mma_bf16(float* c, const unsigned* a, const unsigned* b) {
    asm volatile(
        "mma.sync.aligned.m16n8k16.row.col.f32.bf16.bf16.f32 "
        "{%0,%1,%2,%3}, {%4,%5,%6,%7}, {%8,%9}, {%0,%1,%2,%3};\n"
        : "+f"(c[0]), "+f"(c[1]), "+f"(c[2]), "+f"(c[3])
        : "r"(a[0]), "r"(a[1]), "r"(a[2]), "r"(a[3]), "r"(b[0]), "r"(b[1]));
}

__device__ __forceinline__ void ldsm4(unsigned* r, unsigned addr) {
    asm volatile("ldmatrix.sync.aligned.m8n8.x4.shared.b16 {%0,%1,%2,%3}, [%4];\n"
                 : "=r"(r[0]), "=r"(r[1]), "=r"(r[2]), "=r"(r[3]) : "r"(addr));
}
__device__ __forceinline__ void ldsm4t(unsigned* r, unsigned addr) {
    asm volatile("ldmatrix.sync.aligned.m8n8.x4.trans.shared.b16 {%0,%1,%2,%3}, [%4];\n"
                 : "=r"(r[0]), "=r"(r[1]), "=r"(r[2]), "=r"(r[3]) : "r"(addr));
}

__global__ __launch_bounds__(256)
void gemm_kernel(const float* __restrict__ A, const float* __restrict__ B,
                 const float* __restrict__ bias, float* __restrict__ C,
                 int M, int N, int K, int act) {
    __shared__ __nv_bfloat16 As_hi[BM * SAS];
    __shared__ __nv_bfloat16 As_lo[BM * SAS];
    __shared__ __nv_bfloat16 Bs_hi[BK * SBS];
    __shared__ __nv_bfloat16 Bs_lo[BK * SBS];

    int tid  = threadIdx.x;
    int lane = tid & 31;
    int warp = tid >> 5;
    int bm = blockIdx.y * BM;
    int bn = blockIdx.x * BN;
    int wm0 = (warp >> 2) * 64;   // warp row offset (0 or 64)
    int wn0 = (warp & 3) * 32;    // warp col offset (0,32,64,96)
    int grp = lane >> 2;
    int tig = lane & 3;

    float acc[4][4][4] = {};   // [mfrag][nfrag][c0..c3]

    // ldmatrix per-lane base offsets
    int a_lrow = lane & 15;            // row within 16
    int a_lcol = (lane >> 4) * 8;      // k offset 0/8
    int b_lrow = lane & 15;            // k within 16
    int b_lcol = (lane >> 4) * 8;      // n offset 0/8

    for (int k0 = 0; k0 < K; k0 += BK) {
        // --- stage A tile (128x32 fp32 -> bf16 hi/lo) ---
        #pragma unroll
        for (int pass = 0; pass < 4; pass++) {
            int r  = (tid >> 3) + pass * 32;
            int c4 = (tid & 7) * 4;
            int gr = bm + r;
            float4 av = make_float4(0.f, 0.f, 0.f, 0.f);
            if (gr < M) av = *(const float4*)(A + (size_t)gr * K + k0 + c4);
            unsigned h0, l0, h1, l1;
            split2(av.x, av.y, h0, l0);
            split2(av.z, av.w, h1, l1);
            *(uint2*)(&As_hi[r * SAS + c4]) = make_uint2(h0, h1);
            *(uint2*)(&As_lo[r * SAS + c4]) = make_uint2(l0, l1);
        }
        // --- stage B tile (32x128 fp32 -> bf16 hi/lo), natural [k][n] ---
        #pragma unroll
        for (int pass = 0; pass < 4; pass++) {
            int kr = (tid >> 5) + pass * 8;
            int n4 = (tid & 31) * 4;
            float4 bv = *(const float4*)(B + (size_t)(k0 + kr) * N + bn + n4);
            unsigned h0, l0, h1, l1;
            split2(bv.x, bv.y, h0, l0);
            split2(bv.z, bv.w, h1, l1);
            *(uint2*)(&Bs_hi[kr * SBS + n4]) = make_uint2(h0, h1);
            *(uint2*)(&Bs_lo[kr * SBS + n4]) = make_uint2(l0, l1);
        }
        __syncthreads();

        #pragma unroll
        for (int ks = 0; ks < BK; ks += 16) {
            // B fragments: 2 x (x4.trans) per precision -> 4 n8-frags
            unsigned bh[8], bl[8];
            {
                unsigned off = (unsigned)((ks + b_lrow) * SBS + wn0 + b_lcol) * 2;
                ldsm4t(bh,     su32(Bs_hi) + off);
                ldsm4t(bl,     su32(Bs_lo) + off);
                unsigned off2 = off + 32;  // +16 columns * 2 bytes
                ldsm4t(bh + 4, su32(Bs_hi) + off2);
                ldsm4t(bl + 4, su32(Bs_lo) + off2);
            }
            #pragma unroll
            for (int mf = 0; mf < 4; mf++) {
                unsigned ah[4], al[4];
                unsigned off = (unsigned)((wm0 + mf * 16 + a_lrow) * SAS + ks + a_lcol) * 2;
                ldsm4(ah, su32(As_hi) + off);
                ldsm4(al, su32(As_lo) + off);
                #pragma unroll
                for (int nf = 0; nf < 4; nf++) {
                    mma_bf16(acc[mf][nf], ah, bh + 2 * nf);
                    mma_bf16(acc[mf][nf], ah, bl + 2 * nf);
                    mma_bf16(acc[mf][nf], al, bh + 2 * nf);
                }
            }
        }
        __syncthreads();
    }

    // --- epilogue ---
    #pragma unroll
    for (int mf = 0; mf < 4; mf++) {
        #pragma unroll
        for (int half = 0; half < 2; half++) {
            int gr = bm + wm0 + mf * 16 + grp + half * 8;
            if (gr >= M) continue;
            #pragma unroll
            for (int nf = 0; nf < 4; nf++) {
                int gc = bn + wn0 + nf * 8 + tig * 2;
                float v0 = acc[mf][nf][half * 2 + 0];
                float v1 = acc[mf][nf][half * 2 + 1];
                if (bias) { v0 += bias[gc]; v1 += bias[gc + 1]; }
                if (act == 1) {
                    v0 = 0.5f * v0 * (1.f + erff(v0 * 0.70710678118654752f));
                    v1 = 0.5f * v1 * (1.f + erff(v1 * 0.70710678118654752f));
                }
                *(float2*)(C + (size_t)gr * N + gc) = make_float2(v0, v1);
            }
        }
    }
}

// ---------------------------------------------------------------------------
// Attention: one block per (s, h, b). 128 threads. fp32.
// ---------------------------------------------------------------------------
__global__ __launch_bounds__(128)
void attn_kernel(const float* __restrict__ q, const float* __restrict__ k,
                 const float* __restrict__ v, float* __restrict__ o) {
    int s = blockIdx.x, h = blockIdx.y, b = blockIdx.z;
    __shared__ float qs[HDIM];
    __shared__ float lg[SEQ];
    __shared__ float red[128];
    int tid = threadIdx.x;
    const float scale = 0.125f;

    if (tid < HDIM) qs[tid] = q[(size_t)(b * SEQ + s) * EMB + h * HDIM + tid];
    __syncthreads();

    for (int t = tid; t < SEQ; t += 128) {
        const float* kr = k + (size_t)(b * SEQ + t) * EMB + h * HDIM;
        float acc = 0.f;
        #pragma unroll
        for (int d = 0; d < HDIM; d++) acc += qs[d] * kr[d];
        lg[t] = acc * scale;
    }
    __syncthreads();

    float m = -1e30f;
    for (int t = tid; t < SEQ; t += 128) m = fmaxf(m, lg[t]);
    red[tid] = m; __syncthreads();
    for (int st = 64; st > 0; st >>= 1) {
        if (tid < st) red[tid] = fmaxf(red[tid], red[tid + st]);
        __syncthreads();
    }
    m = red[0];
    __syncthreads();

    float ssum = 0.f;
    for (int t = tid; t < SEQ; t += 128) {
        float e = expf(lg[t] - m);
        lg[t] = e;
        ssum += e;
    }
    red[tid] = ssum; __syncthreads();
    for (int st = 64; st > 0; st >>= 1) {
        if (tid < st) red[tid] += red[tid + st];
        __syncthreads();
    }
    float inv = 1.0f / red[0];
    __syncthreads();

    int d = tid & 63;
    int t0 = (tid < 64) ? 0 : 99;
    int t1 = (tid < 64) ? 99 : SEQ;
    float acc = 0.f;
    for (int t = t0; t < t1; t++)
        acc += lg[t] * v[(size_t)(b * SEQ + t) * EMB + h * HDIM + d];
    red[tid] = acc; __syncthreads();
    if (tid < 64)
        o[(size_t)(b * SEQ + s) * EMB + h * HDIM + tid] = (red[tid] + red[tid + 64]) * inv;
}

// ---------------------------------------------------------------------------
// LayerNorm (optional residual), 1 block / row
// ---------------------------------------------------------------------------
__global__ __launch_bounds__(256)
void ln_kernel(const float* __restrict__ inp, const float* __restrict__ res,
               const float* __restrict__ g, const float* __restrict__ bb,
               float* __restrict__ out, int rows) {
    int r = blockIdx.x;
    if (r >= rows) return;
    int tid = threadIdx.x;
    const float* ip = inp + (size_t)r * EMB;
    const float* rp = res ? res + (size_t)r * EMB : nullptr;
    float v[3];
    float s = 0.f;
    #pragma unroll
    for (int i = 0; i < 3; i++) {
        int c = tid + i * 256;
        float x = ip[c];
        if (rp) x += rp[c];
        v[i] = x;
        s += x;
    }
    __shared__ float sh[256];
    sh[tid] = s; __syncthreads();
    for (int st = 128; st > 0; st >>= 1) { if (tid < st) sh[tid] += sh[tid + st]; __syncthreads(); }
    float mean = sh[0] * (1.f / EMB);
    __syncthreads();
    float s2 = 0.f;
    #pragma unroll
    for (int i = 0; i < 3; i++) { float d = v[i] - mean; s2 += d * d; }
    sh[tid] = s2; __syncthreads();
    for (int st = 128; st > 0; st >>= 1) { if (tid < st) sh[tid] += sh[tid + st]; __syncthreads(); }
    float rstd = rsqrtf(sh[0] * (1.f / EMB) + 1e-5f);
    #pragma unroll
    for (int i = 0; i < 3; i++) {
        int c = tid + i * 256;
        out[(size_t)r * EMB + c] = (v[i] - mean) * rstd * g[c] + bb[c];
    }
}

// ---------------------------------------------------------------------------
// Classifier
// ---------------------------------------------------------------------------
__global__ void clf_kernel(const float* __restrict__ x, const float* __restrict__ w,
                           const float* __restrict__ b, float* __restrict__ out) {
    int idx = threadIdx.x;
    if (idx >= BATCH * 2) return;
    int bb = idx / 2, c = idx % 2;
    const float* xr = x + (size_t)bb * SEQ * EMB;
    float acc = b[c];
    for (int e = 0; e < EMB; e++) acc += xr[e] * w[e * 2 + c];
    out[idx] = acc;
}

// ---------------------------------------------------------------------------
// Host orchestration
// ---------------------------------------------------------------------------
static inline void run_gemm(const float* A, const float* B, const float* bias,
                            float* C, int M, int N, int K, int act) {
    dim3 grid(N / BN, (M + BM - 1) / BM);
    gemm_kernel<<<grid, 256>>>(A, B, bias, C, M, N, K, act);
}

extern "C" void kernel_launch(void* const* d_in, const int* in_sizes, int n_in,
                              void* d_out, int out_size) {
    const float* img     = (const float*)d_in[0];
    const float* patch_w = (const float*)d_in[1];
    const float* patch_b = (const float*)d_in[2];
    const float* cls_tok = (const float*)d_in[3];
    const float* Wq      = (const float*)d_in[4];
    const float* Wk      = (const float*)d_in[5];
    const float* Wv      = (const float*)d_in[6];
    const float* Wo      = (const float*)d_in[7];
    const float* bo      = (const float*)d_in[8];
    const float* ln1_g   = (const float*)d_in[9];
    const float* ln1_b   = (const float*)d_in[10];
    const float* fln_g   = (const float*)d_in[11];
    const float* fln_b   = (const float*)d_in[12];
    const float* fc1_w   = (const float*)d_in[13];
    const float* fc1_b   = (const float*)d_in[14];
    const float* fc2_w   = (const float*)d_in[15];
    const float* fc2_b   = (const float*)d_in[16];
    const float* ln2_g   = (const float*)d_in[17];
    const float* ln2_b   = (const float*)d_in[18];
    const float* clf_w   = (const float*)d_in[19];
    const float* clf_b   = (const float*)d_in[20];
    float* out = (float*)d_out;

    float *x, *q, *k, *v, *o, *t1, *t2, *pos;
    cudaGetSymbolAddress((void**)&x,   g_x);
    cudaGetSymbolAddress((void**)&q,   g_q);
    cudaGetSymbolAddress((void**)&k,   g_k);
    cudaGetSymbolAddress((void**)&v,   g_v);
    cudaGetSymbolAddress((void**)&o,   g_o);
    cudaGetSymbolAddress((void**)&t1,  g_t1);
    cudaGetSymbolAddress((void**)&t2,  g_t2);
    cudaGetSymbolAddress((void**)&pos, g_pos);

    patchify_kernel<<<(PROWS * EMB + 255) / 256, 256>>>(img, t1);
    pos_kernel<<<(SEQ * EMB + 255) / 256, 256>>>(pos);
    run_gemm(t1, patch_w, patch_b, t2, PROWS, EMB, EMB, 0);
    assemble_kernel<<<(ROWS * EMB + 255) / 256, 256>>>(t2, cls_tok, pos, x);

    for (int l = 0; l < LAYERS; l++) {
        const float* wq = Wq + (size_t)l * EMB * EMB;
        const float* wk = Wk + (size_t)l * EMB * EMB;
        const float* wv = Wv + (size_t)l * EMB * EMB;
        const float* wo = Wo + (size_t)l * EMB * EMB;
        const float* w1 = fc1_w + (size_t)l * EMB * FFN;
        const float* w2 = fc2_w + (size_t)l * FFN * EMB;

        run_gemm(x, wq, nullptr, q, ROWS, EMB, EMB, 0);
        run_gemm(x, wk, nullptr, k, ROWS, EMB, EMB, 0);
        run_gemm(x, wv, nullptr, v, ROWS, EMB, EMB, 0);

        dim3 agrid(SEQ, HEADS, BATCH);
        attn_kernel<<<agrid, 128>>>(q, k, v, o);

        run_gemm(o, wo, bo + l * EMB, t2, ROWS, EMB, EMB, 0);
        ln_kernel<<<ROWS, 256>>>(t2, x, ln1_g + l * EMB, ln1_b + l * EMB, x, ROWS);

        ln_kernel<<<ROWS, 256>>>(x, nullptr, fln_g + l * EMB, fln_b + l * EMB, t2, ROWS);
        run_gemm(t2, w1, fc1_b + l * FFN, t1, ROWS, FFN, EMB, 1);
        run_gemm(t1, w2, fc2_b + l * EMB, t2, ROWS, EMB, FFN, 0);
        ln_kernel<<<ROWS, 256>>>(t2, x, ln2_g + l * EMB, ln2_b + l * EMB, x, ROWS);
    }

    clf_kernel<<<1, 64>>>(x, clf_w, clf_b, out);
}

// round 5
// speedup vs baseline: 1.0042x; 1.0042x over previous
#include <cuda_runtime.h>
#include <cuda_bf16.h>
#include <math.h>

// ---------------------------------------------------------------------------
// ViT-Base forward: B=32, S=197, E=768, H=12, D=64, FC=3072, L=12
// Round 4: bf16 hi/lo split GEMM with PRE-SPLIT operands + cp.async
//          double-buffered pipeline. MMA math identical to R3 (verified).
// ---------------------------------------------------------------------------

#define BATCH 32
#define SEQ   197
#define EMB   768
#define HEADS 12
#define HDIM  64
#define FFN   3072
#define LAYERS 12
#define NPATCH 196
#define ROWS  (BATCH * SEQ)      // 6304
#define PROWS (BATCH * NPATCH)   // 6272

#define EE (EMB * EMB)           // 589824
#define EF (EMB * FFN)           // 2359296
#define OFF_PW 0
#define OFF_WQ (OFF_PW + EE)
#define OFF_WK (OFF_WQ + LAYERS * EE)
#define OFF_WV (OFF_WK + LAYERS * EE)
#define OFF_WO (OFF_WV + LAYERS * EE)
#define OFF_F1 (OFF_WO + LAYERS * EE)
#define OFF_F2 (OFF_F1 + LAYERS * EF)
#define W_TOTAL (OFF_F2 + LAYERS * EF)   // 85,524,480

// fp32 scratch
__device__ float g_x  [ROWS * EMB];
__device__ float g_q  [ROWS * EMB];
__device__ float g_k  [ROWS * EMB];
__device__ float g_v  [ROWS * EMB];
__device__ float g_o  [ROWS * EMB];
__device__ float g_t2 [ROWS * EMB];
__device__ float g_t1 [ROWS * FFN];
__device__ float g_pos[SEQ * EMB];
// bf16 hi/lo scratch
__device__ __nv_bfloat16 g_whi[W_TOTAL];
__device__ __nv_bfloat16 g_wlo[W_TOTAL];
__device__ __nv_bfloat16 g_ahi[ROWS * FFN];
__device__ __nv_bfloat16 g_alo[ROWS * FFN];

// ---------------------------------------------------------------------------
// Helpers
// ---------------------------------------------------------------------------
__device__ __forceinline__ unsigned su32(const void* p) {
    return (unsigned)__cvta_generic_to_shared(p);
}

__device__ __forceinline__ void split2(float x, float y, unsigned& hi, unsigned& lo_) {
    __nv_bfloat162 h = __floats2bfloat162_rn(x, y);
    float rx = x - __bfloat162float(h.x);
    float ry = y - __bfloat162float(h.y);
    __nv_bfloat162 l = __floats2bfloat162_rn(rx, ry);
    hi  = *(unsigned*)&h;
    lo_ = *(unsigned*)&l;
}

__device__ __forceinline__ void mma_bf16(float* c, const unsigned* a, const unsigned* b) {
    asm volatile(
        "mma.sync.aligned.m16n8k16.row.col.f32.bf16.bf16.f32 "
        "{%0,%1,%2,%3}, {%4,%5,%6,%7}, {%8,%9}, {%0,%1,%2,%3};\n"
        : "+f"(c[0]), "+f"(c[1]), "+f"(c[2]), "+f"(c[3])
        : "r"(a[0]), "r"(a[1]), "r"(a[2]), "r"(a[3]), "r"(b[0]), "r"(b[1]));
}
__device__ __forceinline__ void ldsm4(unsigned* r, unsigned addr) {
    asm volatile("ldmatrix.sync.aligned.m8n8.x4.shared.b16 {%0,%1,%2,%3}, [%4];\n"
                 : "=r"(r[0]), "=r"(r[1]), "=r"(r[2]), "=r"(r[3]) : "r"(addr));
}
__device__ __forceinline__ void ldsm4t(unsigned* r, unsigned addr) {
    asm volatile("ldmatrix.sync.aligned.m8n8.x4.trans.shared.b16 {%0,%1,%2,%3}, [%4];\n"
                 : "=r"(r[0]), "=r"(r[1]), "=r"(r[2]), "=r"(r[3]) : "r"(addr));
}
__device__ __forceinline__ void cp16(__nv_bfloat16* dst, const __nv_bfloat16* src, bool valid) {
    unsigned s = su32(dst);
    int sz = valid ? 16 : 0;
    asm volatile("cp.async.cg.shared.global [%0], [%1], 16, %2;\n" :: "r"(s), "l"(src), "r"(sz));
}
#define CP_COMMIT() asm volatile("cp.async.commit_group;\n")
template<int N> __device__ __forceinline__ void cp_wait() {
    asm volatile("cp.async.wait_group %0;\n" :: "n"(N));
}

// ---------------------------------------------------------------------------
// fp32 -> bf16 hi/lo split (vectorized, n multiple of 4)
// ---------------------------------------------------------------------------
__global__ void split_kernel(const float* __restrict__ src, __nv_bfloat16* __restrict__ hi,
                             __nv_bfloat16* __restrict__ lo, long n4) {
    long i = (long)blockIdx.x * 256 + threadIdx.x;
    if (i >= n4) return;
    float4 v = ((const float4*)src)[i];
    unsigned h0, l0, h1, l1;
    split2(v.x, v.y, h0, l0);
    split2(v.z, v.w, h1, l1);
    ((uint2*)hi)[i] = make_uint2(h0, h1);
    ((uint2*)lo)[i] = make_uint2(l0, l1);
}

// ---------------------------------------------------------------------------
// Patchify / pos-enc / assemble (unchanged)
// ---------------------------------------------------------------------------
__global__ void patchify_kernel(const float* __restrict__ img, float* __restrict__ out) {
    int idx = blockIdx.x * 256 + threadIdx.x;
    if (idx >= PROWS * EMB) return;
    int col = idx % EMB;
    int row = idx / EMB;
    int b = row / NPATCH, p = row % NPATCH;
    int hh = p / 14, ww = p % 14;
    int c = col % 3;
    int pp = col / 3;
    int p1 = pp / 16, p2 = pp % 16;
    out[idx] = img[((b * 3 + c) * 224 + hh * 16 + p1) * 224 + ww * 16 + p2];
}

__global__ void pos_kernel(float* __restrict__ pos) {
    int idx = blockIdx.x * 256 + threadIdx.x;
    if (idx >= SEQ * EMB) return;
    int t = idx / EMB, j = idx % EMB;
    float val = 0.f;
    if (t > 0) {
        int tok = t - 1;
        int quad = j / 192;
        int i = j % 192;
        float omega = expf(-((float)i / 191.f) * logf(10000.f));
        float coord = (quad < 2) ? (float)(tok % 14) : (float)(tok / 14);
        float arg = coord * omega;
        val = (quad & 1) ? cosf(arg) : sinf(arg);
    }
    pos[idx] = val;
}

__global__ void assemble_kernel(const float* __restrict__ emb, const float* __restrict__ cls,
                                const float* __restrict__ pos, float* __restrict__ x) {
    int idx = blockIdx.x * 256 + threadIdx.x;
    if (idx >= ROWS * EMB) return;
    int e = idx % EMB;
    int bs = idx / EMB;
    int s = bs % SEQ, b = bs / SEQ;
    float val;
    if (s == 0) val = cls[e];
    else        val = emb[(b * NPATCH + s - 1) * EMB + e] + pos[s * EMB + e];
    x[idx] = val;
}

// ---------------------------------------------------------------------------
// Tensor-core GEMM on pre-split bf16 operands, cp.async double-buffered.
// C[M,N] = Ahi@Bhi + Ahi@Blo + Alo@Bhi  (+bias)(+GELU)
// 128x128x32 tile, 8 warps (2m x 4n), 64x32 warp tile. K%32==0, N%128==0.
// ---------------------------------------------------------------------------
#define BM 128
#define BN 128
#define BK 32
#define SAS 40    // A smem row stride (bf16): 80B -> LDSM conflict-free
#define SBS 136   // B smem row stride (bf16): 272B -> LDSM conflict-free
#define A_TILE (BM * SAS)                  // 5120 bf16
#define B_TILE (BK * SBS)                  // 4352 bf16
#define STAGE_ELEMS (2 * A_TILE + 2 * B_TILE)  // 18944 bf16
#define GEMM_SMEM_BYTES (2 * STAGE_ELEMS * 2)  // 75776 B

__global__ __launch_bounds__(256)
void gemm_kernel(const __nv_bfloat16* __restrict__ Ahi, const __nv_bfloat16* __restrict__ Alo,
                 const __nv_bfloat16* __restrict__ Bhi, const __nv_bfloat16* __restrict__ Blo,
                 const float* __restrict__ bias, float* __restrict__ C,
                 int M, int N, int K, int act) {
    extern __shared__ __nv_bfloat16 smem[];

    int tid  = threadIdx.x;
    int lane = tid & 31;
    int warp = tid >> 5;
    int bm = blockIdx.y * BM;
    int bn = blockIdx.x * BN;
    int wm0 = (warp >> 2) * 64;
    int wn0 = (warp & 3) * 32;
    int grp = lane >> 2;
    int tig = lane & 3;

    float acc[4][4][4] = {};

    int a_lrow = lane & 15;
    int a_lcol = (lane >> 4) * 8;
    int b_lrow = lane & 15;
    int b_lcol = (lane >> 4) * 8;

    // staging indices (2 x 16B chunks each for Ahi/Alo/Bhi/Blo per thread)
    int nk = K / BK;

    auto stage_load = [&](int st, int kt) {
        __nv_bfloat16* sAh = smem + st * STAGE_ELEMS;
        __nv_bfloat16* sAl = sAh + A_TILE;
        __nv_bfloat16* sBh = sAl + A_TILE;
        __nv_bfloat16* sBl = sBh + B_TILE;
        int k0 = kt * BK;
        #pragma unroll
        for (int i = 0; i < 2; i++) {
            int ch = tid + i * 256;
            int ar = ch >> 2, ac = (ch & 3) * 8;
            bool v = (bm + ar) < M;
            size_t ga = (size_t)(bm + ar) * K + k0 + ac;
            cp16(sAh + ar * SAS + ac, Ahi + ga, v);
            cp16(sAl + ar * SAS + ac, Alo + ga, v);
            int br = ch >> 4, bc = (ch & 15) * 8;
            size_t gb = (size_t)(k0 + br) * N + bn + bc;
            cp16(sBh + br * SBS + bc, Bhi + gb, true);
            cp16(sBl + br * SBS + bc, Blo + gb, true);
        }
    };

    stage_load(0, 0);
    CP_COMMIT();

    for (int kt = 0; kt < nk; kt++) {
        if (kt + 1 < nk) {
            stage_load((kt + 1) & 1, kt + 1);
            CP_COMMIT();
            cp_wait<1>();
        } else {
            cp_wait<0>();
        }
        __syncthreads();

        int st = kt & 1;
        const __nv_bfloat16* sAh = smem + st * STAGE_ELEMS;
        const __nv_bfloat16* sAl = sAh + A_TILE;
        const __nv_bfloat16* sBh = sAl + A_TILE;
        const __nv_bfloat16* sBl = sBh + B_TILE;
        unsigned baseAh = su32(sAh), baseAl = su32(sAl);
        unsigned baseBh = su32(sBh), baseBl = su32(sBl);

        #pragma unroll
        for (int ks = 0; ks < BK; ks += 16) {
            unsigned bh[8], bl[8];
            {
                unsigned off = (unsigned)((ks + b_lrow) * SBS + wn0 + b_lcol) * 2;
                ldsm4t(bh,     baseBh + off);
                ldsm4t(bl,     baseBl + off);
                unsigned off2 = off + 32;
                ldsm4t(bh + 4, baseBh + off2);
                ldsm4t(bl + 4, baseBl + off2);
            }
            #pragma unroll
            for (int mf = 0; mf < 4; mf++) {
                unsigned ah[4], al[4];
                unsigned off = (unsigned)((wm0 + mf * 16 + a_lrow) * SAS + ks + a_lcol) * 2;
                ldsm4(ah, baseAh + off);
                ldsm4(al, baseAl + off);
                #pragma unroll
                for (int nf = 0; nf < 4; nf++) {
                    mma_bf16(acc[mf][nf], ah, bh + 2 * nf);
                    mma_bf16(acc[mf][nf], ah, bl + 2 * nf);
                    mma_bf16(acc[mf][nf], al, bh + 2 * nf);
                }
            }
        }
        __syncthreads();
    }

    // epilogue
    #pragma unroll
    for (int mf = 0; mf < 4; mf++) {
        #pragma unroll
        for (int half = 0; half < 2; half++) {
            int gr = bm + wm0 + mf * 16 + grp + half * 8;
            if (gr >= M) continue;
            #pragma unroll
            for (int nf = 0; nf < 4; nf++) {
                int gc = bn + wn0 + nf * 8 + tig * 2;
                float v0 = acc[mf][nf][half * 2 + 0];
                float v1 = acc[mf][nf][half * 2 + 1];
                if (bias) { v0 += bias[gc]; v1 += bias[gc + 1]; }
                if (act == 1) {
                    v0 = 0.5f * v0 * (1.f + erff(v0 * 0.70710678118654752f));
                    v1 = 0.5f * v1 * (1.f + erff(v1 * 0.70710678118654752f));
                }
                *(float2*)(C + (size_t)gr * N + gc) = make_float2(v0, v1);
            }
        }
    }
}

// ---------------------------------------------------------------------------
// Attention: one block per (s, h, b). 128 threads. fp32.
// ---------------------------------------------------------------------------
__global__ __launch_bounds__(128)
void attn_kernel(const float* __restrict__ q, const float* __restrict__ k,
                 const float* __restrict__ v, float* __restrict__ o) {
    int s = blockIdx.x, h = blockIdx.y, b = blockIdx.z;
    __shared__ float qs[HDIM];
    __shared__ float lg[SEQ];
    __shared__ float red[128];
    int tid = threadIdx.x;
    const float scale = 0.125f;

    if (tid < HDIM) qs[tid] = q[(size_t)(b * SEQ + s) * EMB + h * HDIM + tid];
    __syncthreads();

    for (int t = tid; t < SEQ; t += 128) {
        const float* kr = k + (size_t)(b * SEQ + t) * EMB + h * HDIM;
        float acc = 0.f;
        #pragma unroll
        for (int d = 0; d < HDIM; d++) acc += qs[d] * kr[d];
        lg[t] = acc * scale;
    }
    __syncthreads();

    float m = -1e30f;
    for (int t = tid; t < SEQ; t += 128) m = fmaxf(m, lg[t]);
    red[tid] = m; __syncthreads();
    for (int st = 64; st > 0; st >>= 1) {
        if (tid < st) red[tid] = fmaxf(red[tid], red[tid + st]);
        __syncthreads();
    }
    m = red[0];
    __syncthreads();

    float ssum = 0.f;
    for (int t = tid; t < SEQ; t += 128) {
        float e = expf(lg[t] - m);
        lg[t] = e;
        ssum += e;
    }
    red[tid] = ssum; __syncthreads();
    for (int st = 64; st > 0; st >>= 1) {
        if (tid < st) red[tid] += red[tid + st];
        __syncthreads();
    }
    float inv = 1.0f / red[0];
    __syncthreads();

    int d = tid & 63;
    int t0 = (tid < 64) ? 0 : 99;
    int t1 = (tid < 64) ? 99 : SEQ;
    float acc = 0.f;
    for (int t = t0; t < t1; t++)
        acc += lg[t] * v[(size_t)(b * SEQ + t) * EMB + h * HDIM + d];
    red[tid] = acc; __syncthreads();
    if (tid < 64)
        o[(size_t)(b * SEQ + s) * EMB + h * HDIM + tid] = (red[tid] + red[tid + 64]) * inv;
}

// ---------------------------------------------------------------------------
// LayerNorm (optional residual)
// ---------------------------------------------------------------------------
__global__ __launch_bounds__(256)
void ln_kernel(const float* __restrict__ inp, const float* __restrict__ res,
               const float* __restrict__ g, const float* __restrict__ bb,
               float* __restrict__ out, int rows) {
    int r = blockIdx.x;
    if (r >= rows) return;
    int tid = threadIdx.x;
    const float* ip = inp + (size_t)r * EMB;
    const float* rp = res ? res + (size_t)r * EMB : nullptr;
    float v[3];
    float s = 0.f;
    #pragma unroll
    for (int i = 0; i < 3; i++) {
        int c = tid + i * 256;
        float x = ip[c];
        if (rp) x += rp[c];
        v[i] = x;
        s += x;
    }
    __shared__ float sh[256];
    sh[tid] = s; __syncthreads();
    for (int st = 128; st > 0; st >>= 1) { if (tid < st) sh[tid] += sh[tid + st]; __syncthreads(); }
    float mean = sh[0] * (1.f / EMB);
    __syncthreads();
    float s2 = 0.f;
    #pragma unroll
    for (int i = 0; i < 3; i++) { float d = v[i] - mean; s2 += d * d; }
    sh[tid] = s2; __syncthreads();
    for (int st = 128; st > 0; st >>= 1) { if (tid < st) sh[tid] += sh[tid + st]; __syncthreads(); }
    float rstd = rsqrtf(sh[0] * (1.f / EMB) + 1e-5f);
    #pragma unroll
    for (int i = 0; i < 3; i++) {
        int c = tid + i * 256;
        out[(size_t)r * EMB + c] = (v[i] - mean) * rstd * g[c] + bb[c];
    }
}

// ---------------------------------------------------------------------------
// Classifier
// ---------------------------------------------------------------------------
__global__ void clf_kernel(const float* __restrict__ x, const float* __restrict__ w,
                           const float* __restrict__ b, float* __restrict__ out) {
    int idx = threadIdx.x;
    if (idx >= BATCH * 2) return;
    int bb = idx / 2, c = idx % 2;
    const float* xr = x + (size_t)bb * SEQ * EMB;
    float acc = b[c];
    for (int e = 0; e < EMB; e++) acc += xr[e] * w[e * 2 + c];
    out[idx] = acc;
}

// ---------------------------------------------------------------------------
// Host orchestration
// ---------------------------------------------------------------------------
static inline void run_split(const float* src, __nv_bfloat16* hi, __nv_bfloat16* lo, long n) {
    long n4 = n / 4;
    split_kernel<<<(unsigned)((n4 + 255) / 256), 256>>>(src, hi, lo, n4);
}

static inline void run_gemm(const __nv_bfloat16* Ahi, const __nv_bfloat16* Alo,
                            const __nv_bfloat16* Bhi, const __nv_bfloat16* Blo,
                            const float* bias, float* C, int M, int N, int K, int act) {
    dim3 grid(N / BN, (M + BM - 1) / BM);
    gemm_kernel<<<grid, 256, GEMM_SMEM_BYTES>>>(Ahi, Alo, Bhi, Blo, bias, C, M, N, K, act);
}

extern "C" void kernel_launch(void* const* d_in, const int* in_sizes, int n_in,
                              void* d_out, int out_size) {
    const float* img     = (const float*)d_in[0];
    const float* patch_w = (const float*)d_in[1];
    const float* patch_b = (const float*)d_in[2];
    const float* cls_tok = (const float*)d_in[3];
    const float* Wq      = (const float*)d_in[4];
    const float* Wk      = (const float*)d_in[5];
    const float* Wv      = (const float*)d_in[6];
    const float* Wo      = (const float*)d_in[7];
    const float* bo      = (const float*)d_in[8];
    const float* ln1_g   = (const float*)d_in[9];
    const float* ln1_b   = (const float*)d_in[10];
    const float* fln_g   = (const float*)d_in[11];
    const float* fln_b   = (const float*)d_in[12];
    const float* fc1_w   = (const float*)d_in[13];
    const float* fc1_b   = (const float*)d_in[14];
    const float* fc2_w   = (const float*)d_in[15];
    const float* fc2_b   = (const float*)d_in[16];
    const float* ln2_g   = (const float*)d_in[17];
    const float* ln2_b   = (const float*)d_in[18];
    const float* clf_w   = (const float*)d_in[19];
    const float* clf_b   = (const float*)d_in[20];
    float* out = (float*)d_out;

    cudaFuncSetAttribute(gemm_kernel, cudaFuncAttributeMaxDynamicSharedMemorySize,
                         GEMM_SMEM_BYTES);

    float *x, *q, *k, *v, *o, *t1, *t2, *pos;
    __nv_bfloat16 *whi, *wlo, *ahi, *alo;
    cudaGetSymbolAddress((void**)&x,   g_x);
    cudaGetSymbolAddress((void**)&q,   g_q);
    cudaGetSymbolAddress((void**)&k,   g_k);
    cudaGetSymbolAddress((void**)&v,   g_v);
    cudaGetSymbolAddress((void**)&o,   g_o);
    cudaGetSymbolAddress((void**)&t1,  g_t1);
    cudaGetSymbolAddress((void**)&t2,  g_t2);
    cudaGetSymbolAddress((void**)&pos, g_pos);
    cudaGetSymbolAddress((void**)&whi, g_whi);
    cudaGetSymbolAddress((void**)&wlo, g_wlo);
    cudaGetSymbolAddress((void**)&ahi, g_ahi);
    cudaGetSymbolAddress((void**)&alo, g_alo);

    // --- weight pre-split (once per launch) ---
    run_split(patch_w, whi + OFF_PW, wlo + OFF_PW, EE);
    run_split(Wq,      whi + OFF_WQ, wlo + OFF_WQ, (long)LAYERS * EE);
    run_split(Wk,      whi + OFF_WK, wlo + OFF_WK, (long)LAYERS * EE);
    run_split(Wv,      whi + OFF_WV, wlo + OFF_WV, (long)LAYERS * EE);
    run_split(Wo,      whi + OFF_WO, wlo + OFF_WO, (long)LAYERS * EE);
    run_split(fc1_w,   whi + OFF_F1, wlo + OFF_F1, (long)LAYERS * EF);
    run_split(fc2_w,   whi + OFF_F2, wlo + OFF_F2, (long)LAYERS * EF);

    // --- embedding ---
    patchify_kernel<<<(PROWS * EMB + 255) / 256, 256>>>(img, t1);
    pos_kernel<<<(SEQ * EMB + 255) / 256, 256>>>(pos);
    run_split(t1, ahi, alo, (long)PROWS * EMB);
    run_gemm(ahi, alo, whi + OFF_PW, wlo + OFF_PW, patch_b, t2, PROWS, EMB, EMB, 0);
    assemble_kernel<<<(ROWS * EMB + 255) / 256, 256>>>(t2, cls_tok, pos, x);

    // --- transformer layers ---
    for (int l = 0; l < LAYERS; l++) {
        const __nv_bfloat16* wqh = whi + OFF_WQ + (size_t)l * EE;
        const __nv_bfloat16* wql = wlo + OFF_WQ + (size_t)l * EE;
        const __nv_bfloat16* wkh = whi + OFF_WK + (size_t)l * EE;
        const __nv_bfloat16* wkl = wlo + OFF_WK + (size_t)l * EE;
        const __nv_bfloat16* wvh = whi + OFF_WV + (size_t)l * EE;
        const __nv_bfloat16* wvl = wlo + OFF_WV + (size_t)l * EE;
        const __nv_bfloat16* woh = whi + OFF_WO + (size_t)l * EE;
        const __nv_bfloat16* wol = wlo + OFF_WO + (size_t)l * EE;
        const __nv_bfloat16* w1h = whi + OFF_F1 + (size_t)l * EF;
        const __nv_bfloat16* w1l = wlo + OFF_F1 + (size_t)l * EF;
        const __nv_bfloat16* w2h = whi + OFF_F2 + (size_t)l * EF;
        const __nv_bfloat16* w2l = wlo + OFF_F2 + (size_t)l * EF;

        run_split(x, ahi, alo, (long)ROWS * EMB);
        run_gemm(ahi, alo, wqh, wql, nullptr, q, ROWS, EMB, EMB, 0);
        run_gemm(ahi, alo, wkh, wkl, nullptr, k, ROWS, EMB, EMB, 0);
        run_gemm(ahi, alo, wvh, wvl, nullptr, v, ROWS, EMB, EMB, 0);

        dim3 agrid(SEQ, HEADS, BATCH);
        attn_kernel<<<agrid, 128>>>(q, k, v, o);

        run_split(o, ahi, alo, (long)ROWS * EMB);
        run_gemm(ahi, alo, woh, wol, bo + l * EMB, t2, ROWS, EMB, EMB, 0);
        ln_kernel<<<ROWS, 256>>>(t2, x, ln1_g + l * EMB, ln1_b + l * EMB, x, ROWS);

        ln_kernel<<<ROWS, 256>>>(x, nullptr, fln_g + l * EMB, fln_b + l * EMB, t2, ROWS);
        run_split(t2, ahi, alo, (long)ROWS * EMB);
        run_gemm(ahi, alo, w1h, w1l, fc1_b + l * FFN, t1, ROWS, FFN, EMB, 1);
        run_split(t1, ahi, alo, (long)ROWS * FFN);
        run_gemm(ahi, alo, w2h, w2l, fc2_b + l * EMB, t2, ROWS, EMB, FFN, 0);
        ln_kernel<<<ROWS, 256>>>(t2, x, ln2_g + l * EMB, ln2_b + l * EMB, x, ROWS);
    }

    clf_kernel<<<1, 64>>>(x, clf_w, clf_b, out);
}

// round 9
// speedup vs baseline: 3.0381x; 3.0253x over previous
#include <cuda_runtime.h>
#include <math.h>
#include <stdint.h>

// ---------------------------------------------------------------------------
// ViT-Base forward: B=32, S=197, E=768, H=12, D=64, FC=3072, L=12
// Round 8: no usable tensor HW on this toolchain (tcgen05 blocked, mma.sync
// emulated). Use packed fp32 fma.rn.f32x2 (2x FFMA rate) SIMT GEMM + tiled
// attention. Full fp32 precision end-to-end.
// ---------------------------------------------------------------------------

#define BATCH 32
#define SEQ   197
#define EMB   768
#define HEADS 12
#define HDIM  64
#define FFN   3072
#define LAYERS 12
#define NPATCH 196
#define ROWS  (BATCH * SEQ)      // 6304
#define PROWS (BATCH * NPATCH)   // 6272

// Scratch
__device__ float g_x  [ROWS * EMB];
__device__ float g_q  [ROWS * EMB];
__device__ float g_k  [ROWS * EMB];
__device__ float g_v  [ROWS * EMB];
__device__ float g_o  [ROWS * EMB];
__device__ float g_t2 [ROWS * EMB];
__device__ float g_t1 [ROWS * FFN];
__device__ float g_pos[SEQ * EMB];

// ---------------------------------------------------------------------------
// Packed f32x2 helpers (Blackwell packed fp32 pipe: 2 FMAs per issue)
// ---------------------------------------------------------------------------
__device__ __forceinline__ void fma2(unsigned long long& acc, unsigned long long a,
                                     unsigned long long b) {
    asm("fma.rn.f32x2 %0, %1, %2, %0;" : "+l"(acc) : "l"(a), "l"(b));
}
__device__ __forceinline__ unsigned long long pack2(float x) {
    unsigned long long r;
    asm("mov.b64 %0, {%1, %1};" : "=l"(r) : "f"(x));
    return r;
}
__device__ __forceinline__ float2 unpack2(unsigned long long v) {
    float2 f;
    asm("mov.b64 {%0, %1}, %2;" : "=f"(f.x), "=f"(f.y) : "l"(v));
    return f;
}
__device__ __forceinline__ float gelu(float v) {
    return 0.5f * v * (1.f + erff(v * 0.70710678118654752f));
}

// ---------------------------------------------------------------------------
// Patchify
// ---------------------------------------------------------------------------
__global__ void patchify_kernel(const float* __restrict__ img, float* __restrict__ out) {
    int idx = blockIdx.x * 256 + threadIdx.x;
    if (idx >= PROWS * EMB) return;
    int col = idx % EMB;
    int row = idx / EMB;
    int b = row / NPATCH, p = row % NPATCH;
    int hh = p / 14, ww = p % 14;
    int c = col % 3;
    int pp = col / 3;
    int p1 = pp / 16, p2 = pp % 16;
    out[idx] = img[((b * 3 + c) * 224 + hh * 16 + p1) * 224 + ww * 16 + p2];
}

// ---------------------------------------------------------------------------
// 2D sincos positional encoding
// ---------------------------------------------------------------------------
__global__ void pos_kernel(float* __restrict__ pos) {
    int idx = blockIdx.x * 256 + threadIdx.x;
    if (idx >= SEQ * EMB) return;
    int t = idx / EMB, j = idx % EMB;
    float val = 0.f;
    if (t > 0) {
        int tok = t - 1;
        int quad = j / 192;
        int i = j % 192;
        float omega = expf(-((float)i / 191.f) * logf(10000.f));
        float coord = (quad < 2) ? (float)(tok % 14) : (float)(tok / 14);
        float arg = coord * omega;
        val = (quad & 1) ? cosf(arg) : sinf(arg);
    }
    pos[idx] = val;
}

// ---------------------------------------------------------------------------
// Assemble token stream
// ---------------------------------------------------------------------------
__global__ void assemble_kernel(const float* __restrict__ emb, const float* __restrict__ cls,
                                const float* __restrict__ pos, float* __restrict__ x) {
    int idx = blockIdx.x * 256 + threadIdx.x;
    if (idx >= ROWS * EMB) return;
    int e = idx % EMB;
    int bs = idx / EMB;
    int s = bs % SEQ, b = bs / SEQ;
    float val;
    if (s == 0) val = cls[e];
    else        val = emb[(b * NPATCH + s - 1) * EMB + e] + pos[s * EMB + e];
    x[idx] = val;
}

// ---------------------------------------------------------------------------
// fp32 GEMM via fma.rn.f32x2: C[M,N] = A[M,K] @ B[K,N] (+bias)(+GELU)
// 128x128x16 tile, 256 threads, 8x8 microtile (4 f32x2-pairs wide),
// reg-staged double-buffered smem. K%16==0, N%128==0, M arbitrary.
// ---------------------------------------------------------------------------
#define BM 128
#define BN 128
#define BK 16
#define STG 4096   // floats per stage: A 16x128 + B 16x128

__global__ __launch_bounds__(256, 2)
void gemm_kernel(const float* __restrict__ A, const float* __restrict__ B,
                 const float* __restrict__ bias, float* __restrict__ C,
                 int M, int N, int K, int act) {
    __shared__ float sm[2 * STG];
    int tid = threadIdx.x;
    int tx = tid & 15, ty = tid >> 4;
    int bm = blockIdx.y * BM, bn = blockIdx.x * BN;

    int ar[2], ac[2], br[2], bc[2];
    float4 pa[2], pb[2];
    #pragma unroll
    for (int i = 0; i < 2; i++) {
        int c = tid + i * 256;
        ar[i] = c >> 2;  ac[i] = (c & 3) * 4;    // A: 128 rows x 16 cols
        br[i] = c >> 5;  bc[i] = (c & 31) * 4;   // B: 16 rows x 128 cols
    }

    auto ldg = [&](int k0) {
        #pragma unroll
        for (int i = 0; i < 2; i++) {
            if (bm + ar[i] < M)
                pa[i] = *(const float4*)(A + (size_t)(bm + ar[i]) * K + k0 + ac[i]);
            else
                pa[i] = make_float4(0.f, 0.f, 0.f, 0.f);
            pb[i] = *(const float4*)(B + (size_t)(k0 + br[i]) * N + bn + bc[i]);
        }
    };
    auto sts = [&](int s) {
        float* as = sm + s * STG;
        float* bs = as + 2048;
        #pragma unroll
        for (int i = 0; i < 2; i++) {
            as[(ac[i] + 0) * BM + ar[i]] = pa[i].x;   // transpose A -> [k][m]
            as[(ac[i] + 1) * BM + ar[i]] = pa[i].y;
            as[(ac[i] + 2) * BM + ar[i]] = pa[i].z;
            as[(ac[i] + 3) * BM + ar[i]] = pa[i].w;
            *(float4*)(bs + br[i] * BN + bc[i]) = pb[i];
        }
    };

    unsigned long long acc[8][4];
    #pragma unroll
    for (int i = 0; i < 8; i++)
        #pragma unroll
        for (int j = 0; j < 4; j++) acc[i][j] = 0ull;

    ldg(0); sts(0); __syncthreads();
    int nk = K / BK;
    for (int kt = 0; kt < nk; kt++) {
        if (kt + 1 < nk) ldg((kt + 1) * BK);
        const float* as = sm + (kt & 1) * STG;
        const float* bs = as + 2048;
        #pragma unroll
        for (int k = 0; k < BK; k++) {
            float4 a0 = *(const float4*)(as + k * BM + ty * 4);
            float4 a1 = *(const float4*)(as + k * BM + ty * 4 + 64);
            unsigned long long b0 = *(const unsigned long long*)(bs + k * BN + tx * 4);
            unsigned long long b1 = *(const unsigned long long*)(bs + k * BN + tx * 4 + 2);
            unsigned long long b2 = *(const unsigned long long*)(bs + k * BN + tx * 4 + 64);
            unsigned long long b3 = *(const unsigned long long*)(bs + k * BN + tx * 4 + 66);
            unsigned long long av[8];
            av[0] = pack2(a0.x); av[1] = pack2(a0.y); av[2] = pack2(a0.z); av[3] = pack2(a0.w);
            av[4] = pack2(a1.x); av[5] = pack2(a1.y); av[6] = pack2(a1.z); av[7] = pack2(a1.w);
            #pragma unroll
            for (int i = 0; i < 8; i++) {
                fma2(acc[i][0], av[i], b0);
                fma2(acc[i][1], av[i], b1);
                fma2(acc[i][2], av[i], b2);
                fma2(acc[i][3], av[i], b3);
            }
        }
        if (kt + 1 < nk) sts((kt + 1) & 1);
        __syncthreads();
    }

    // epilogue: rows ty*4 + (i&3) + (i>>2)*64; col pairs tx*4 + {0,2,64,66}
    #pragma unroll
    for (int i = 0; i < 8; i++) {
        int gr = bm + ty * 4 + (i & 3) + (i >> 2) * 64;
        if (gr >= M) continue;
        float* crow = C + (size_t)gr * N;
        #pragma unroll
        for (int j = 0; j < 4; j++) {
            int gc = bn + tx * 4 + (j & 1) * 2 + (j >> 1) * 64;
            float2 v = unpack2(acc[i][j]);
            if (bias) { v.x += bias[gc]; v.y += bias[gc + 1]; }
            if (act)  { v.x = gelu(v.x); v.y = gelu(v.y); }
            *(float2*)(crow + gc) = v;
        }
    }
}

// ---------------------------------------------------------------------------
// Tiled attention: block = (16-query tile, head, batch). 256 threads.
// K head staged in smem (padded stride, conflict-free), V streamed (L1 reuse).
// ---------------------------------------------------------------------------
#define QT   16
#define KSTR 68            // padded row stride (floats) for Ks/Qs
#define LSTR 208           // padded logits stride
#define ATT_QS   (SEQ * KSTR)             // float offsets
#define ATT_LG   (ATT_QS + QT * KSTR)
#define ATT_INV  (ATT_LG + QT * LSTR)
#define ATT_SMEM ((ATT_INV + 16) * 4)     // bytes (~71.3 KB)

__global__ __launch_bounds__(256)
void attn_kernel(const float* __restrict__ q, const float* __restrict__ k,
                 const float* __restrict__ v, float* __restrict__ o) {
    extern __shared__ float sm[];
    float* Ks  = sm;
    float* Qs  = sm + ATT_QS;
    float* lg  = sm + ATT_LG;
    float* inv = sm + ATT_INV;
    int qt = blockIdx.x, h = blockIdx.y, b = blockIdx.z;
    int tid = threadIdx.x;
    const float scale = 0.125f;

    // stage K head [197][64] -> Ks (padded)
    for (int idx = tid; idx < SEQ * 16; idx += 256) {
        int t = idx >> 4, d4 = (idx & 15) * 4;
        *(float4*)(Ks + t * KSTR + d4) =
            *(const float4*)(k + (size_t)(b * SEQ + t) * EMB + h * HDIM + d4);
    }
    // stage Q tile [16][64]
    {
        int t = tid >> 4, d4 = (tid & 15) * 4;
        int s = qt * QT + t;
        float4 qv = make_float4(0.f, 0.f, 0.f, 0.f);
        if (s < SEQ) qv = *(const float4*)(q + (size_t)(b * SEQ + s) * EMB + h * HDIM + d4);
        *(float4*)(Qs + t * KSTR + d4) = qv;
    }
    __syncthreads();

    // logits: thread (q = tid>>4, g = tid&15), t = g + 16*pass
    int qq = tid >> 4, g = tid & 15;
    for (int pass = 0; pass < 13; pass++) {
        int t = g + pass * 16;
        if (t < SEQ) {
            float acc = 0.f;
            #pragma unroll
            for (int d4 = 0; d4 < HDIM; d4 += 4) {
                float4 qv = *(float4*)(Qs + qq * KSTR + d4);
                float4 kv = *(float4*)(Ks + t * KSTR + d4);
                acc += qv.x * kv.x + qv.y * kv.y + qv.z * kv.z + qv.w * kv.w;
            }
            lg[qq * LSTR + t] = acc * scale;
        }
    }
    __syncthreads();

    // softmax: warp w handles queries 2w, 2w+1
    int warp = tid >> 5, lane = tid & 31;
    #pragma unroll
    for (int qi = warp * 2; qi < warp * 2 + 2; qi++) {
        float m = -1e30f;
        for (int t = lane; t < SEQ; t += 32) m = fmaxf(m, lg[qi * LSTR + t]);
        #pragma unroll
        for (int s = 16; s; s >>= 1) m = fmaxf(m, __shfl_xor_sync(0xFFFFFFFFu, m, s));
        float sum = 0.f;
        for (int t = lane; t < SEQ; t += 32) {
            float e = expf(lg[qi * LSTR + t] - m);
            lg[qi * LSTR + t] = e;
            sum += e;
        }
        #pragma unroll
        for (int s = 16; s; s >>= 1) sum += __shfl_xor_sync(0xFFFFFFFFu, sum, s);
        if (lane == 0) inv[qi] = 1.0f / sum;
    }
    __syncthreads();

    // AV: thread (qq, dgroup) accumulates 4 output dims
    {
        int d4 = (tid & 15) * 4;
        float4 accv = make_float4(0.f, 0.f, 0.f, 0.f);
        const float* vb = v + (size_t)(b * SEQ) * EMB + h * HDIM + d4;
        const float* lr = lg + qq * LSTR;
        for (int t = 0; t < SEQ; t++) {
            float w = lr[t];
            float4 vv = *(const float4*)(vb + (size_t)t * EMB);
            accv.x += w * vv.x; accv.y += w * vv.y;
            accv.z += w * vv.z; accv.w += w * vv.w;
        }
        int s = qt * QT + qq;
        if (s < SEQ) {
            float iv = inv[qq];
            accv.x *= iv; accv.y *= iv; accv.z *= iv; accv.w *= iv;
            *(float4*)(o + (size_t)(b * SEQ + s) * EMB + h * HDIM + d4) = accv;
        }
    }
}

// ---------------------------------------------------------------------------
// LayerNorm (optional residual), 1 block / row
// ---------------------------------------------------------------------------
__global__ __launch_bounds__(256)
void ln_kernel(const float* __restrict__ inp, const float* __restrict__ res,
               const float* __restrict__ g, const float* __restrict__ bb,
               float* __restrict__ out, int rows) {
    int r = blockIdx.x;
    if (r >= rows) return;
    int tid = threadIdx.x;
    const float* ip = inp + (size_t)r * EMB;
    const float* rp = res ? res + (size_t)r * EMB : nullptr;
    float v[3];
    float s = 0.f;
    #pragma unroll
    for (int i = 0; i < 3; i++) {
        int c = tid + i * 256;
        float x = ip[c];
        if (rp) x += rp[c];
        v[i] = x;
        s += x;
    }
    __shared__ float sh[256];
    sh[tid] = s; __syncthreads();
    for (int st = 128; st > 0; st >>= 1) { if (tid < st) sh[tid] += sh[tid + st]; __syncthreads(); }
    float mean = sh[0] * (1.f / EMB);
    __syncthreads();
    float s2 = 0.f;
    #pragma unroll
    for (int i = 0; i < 3; i++) { float d = v[i] - mean; s2 += d * d; }
    sh[tid] = s2; __syncthreads();
    for (int st = 128; st > 0; st >>= 1) { if (tid < st) sh[tid] += sh[tid + st]; __syncthreads(); }
    float rstd = rsqrtf(sh[0] * (1.f / EMB) + 1e-5f);
    #pragma unroll
    for (int i = 0; i < 3; i++) {
        int c = tid + i * 256;
        out[(size_t)r * EMB + c] = (v[i] - mean) * rstd * g[c] + bb[c];
    }
}

// ---------------------------------------------------------------------------
// Classifier
// ---------------------------------------------------------------------------
__global__ void clf_kernel(const float* __restrict__ x, const float* __restrict__ w,
                           const float* __restrict__ b, float* __restrict__ out) {
    int idx = threadIdx.x;
    if (idx >= BATCH * 2) return;
    int bb = idx / 2, c = idx % 2;
    const float* xr = x + (size_t)bb * SEQ * EMB;
    float acc = b[c];
    for (int e = 0; e < EMB; e++) acc += xr[e] * w[e * 2 + c];
    out[idx] = acc;
}

// ---------------------------------------------------------------------------
// Host orchestration
// ---------------------------------------------------------------------------
static inline void run_gemm(const float* A, const float* B, const float* bias,
                            float* C, int M, int N, int K, int act) {
    dim3 grid(N / BN, (M + BM - 1) / BM);
    gemm_kernel<<<grid, 256>>>(A, B, bias, C, M, N, K, act);
}

extern "C" void kernel_launch(void* const* d_in, const int* in_sizes, int n_in,
                              void* d_out, int out_size) {
    const float* img     = (const float*)d_in[0];
    const float* patch_w = (const float*)d_in[1];
    const float* patch_b = (const float*)d_in[2];
    const float* cls_tok = (const float*)d_in[3];
    const float* Wq      = (const float*)d_in[4];
    const float* Wk      = (const float*)d_in[5];
    const float* Wv      = (const float*)d_in[6];
    const float* Wo      = (const float*)d_in[7];
    const float* bo      = (const float*)d_in[8];
    const float* ln1_g   = (const float*)d_in[9];
    const float* ln1_b   = (const float*)d_in[10];
    const float* fln_g   = (const float*)d_in[11];
    const float* fln_b   = (const float*)d_in[12];
    const float* fc1_w   = (const float*)d_in[13];
    const float* fc1_b   = (const float*)d_in[14];
    const float* fc2_w   = (const float*)d_in[15];
    const float* fc2_b   = (const float*)d_in[16];
    const float* ln2_g   = (const float*)d_in[17];
    const float* ln2_b   = (const float*)d_in[18];
    const float* clf_w   = (const float*)d_in[19];
    const float* clf_b   = (const float*)d_in[20];
    float* out = (float*)d_out;

    cudaFuncSetAttribute(attn_kernel, cudaFuncAttributeMaxDynamicSharedMemorySize, ATT_SMEM);

    float *x, *q, *k, *v, *o, *t1, *t2, *pos;
    cudaGetSymbolAddress((void**)&x,   g_x);
    cudaGetSymbolAddress((void**)&q,   g_q);
    cudaGetSymbolAddress((void**)&k,   g_k);
    cudaGetSymbolAddress((void**)&v,   g_v);
    cudaGetSymbolAddress((void**)&o,   g_o);
    cudaGetSymbolAddress((void**)&t1,  g_t1);
    cudaGetSymbolAddress((void**)&t2,  g_t2);
    cudaGetSymbolAddress((void**)&pos, g_pos);

    // --- Embedding ---
    patchify_kernel<<<(PROWS * EMB + 255) / 256, 256>>>(img, t1);
    pos_kernel<<<(SEQ * EMB + 255) / 256, 256>>>(pos);
    run_gemm(t1, patch_w, patch_b, t2, PROWS, EMB, EMB, 0);
    assemble_kernel<<<(ROWS * EMB + 255) / 256, 256>>>(t2, cls_tok, pos, x);

    // --- Transformer layers ---
    for (int l = 0; l < LAYERS; l++) {
        const float* wq = Wq + (size_t)l * EMB * EMB;
        const float* wk = Wk + (size_t)l * EMB * EMB;
        const float* wv = Wv + (size_t)l * EMB * EMB;
        const float* wo = Wo + (size_t)l * EMB * EMB;
        const float* w1 = fc1_w + (size_t)l * EMB * FFN;
        const float* w2 = fc2_w + (size_t)l * FFN * EMB;

        run_gemm(x, wq, nullptr, q, ROWS, EMB, EMB, 0);
        run_gemm(x, wk, nullptr, k, ROWS, EMB, EMB, 0);
        run_gemm(x, wv, nullptr, v, ROWS, EMB, EMB, 0);

        dim3 agrid((SEQ + QT - 1) / QT, HEADS, BATCH);
        attn_kernel<<<agrid, 256, ATT_SMEM>>>(q, k, v, o);

        run_gemm(o, wo, bo + l * EMB, t2, ROWS, EMB, EMB, 0);
        ln_kernel<<<ROWS, 256>>>(t2, x, ln1_g + l * EMB, ln1_b + l * EMB, x, ROWS);

        ln_kernel<<<ROWS, 256>>>(x, nullptr, fln_g + l * EMB, fln_b + l * EMB, t2, ROWS);
        run_gemm(t2, w1, fc1_b + l * FFN, t1, ROWS, FFN, EMB, 1);
        run_gemm(t1, w2, fc2_b + l * EMB, t2, ROWS, EMB, FFN, 0);
        ln_kernel<<<ROWS, 256>>>(t2, x, ln2_g + l * EMB, ln2_b + l * EMB, x, ROWS);
    }

    // --- Classifier head ---
    clf_kernel<<<1, 64>>>(x, clf_w, clf_b, out);
}